// round 3
// baseline (speedup 1.0000x reference)
#include <cuda_runtime.h>
#include <cuda_bf16.h>

// Problem constants (fixed by setup_inputs): B=8, D=1024, comp 24x24, orig 96x96,
// KERNEL=STRIDE=4, PAD=0 -> all window slots valid, non-overlapping tiling.
constexpr int B_   = 8;
constexpr int D_   = 1024;
constexpr int CH_  = 24, CW_ = 24;
constexpr int OH_  = 96, OW_ = 96;
constexpr int N_   = CH_ * CW_;     // 576 compressed tokens per batch
constexpr int NB_  = B_ * N_;       // 4608 blocks
constexpr int KER_ = 4;
constexpr int WIN_ = KER_ * KER_;   // 16 window slots
constexpr float EPS_ = 1e-12f;

// Zero-initialized device globals; the finishing block resets them so every
// graph replay starts from a clean state (no allocation, no host sync).
__device__ float        g_accum = 0.0f;
__device__ unsigned int g_count = 0u;

__global__ __launch_bounds__(512, 3)
void rf_sim_kernel(const float* __restrict__ comp, const float* __restrict__ orig,
                   float* __restrict__ out) {
    __shared__ float s_sims[16];

    const int blk  = blockIdx.x;      // linear (b, token) index
    const int b    = blk / N_;
    const int t    = blk - b * N_;
    const int Hc   = t / CW_;
    const int Wc   = t - Hc * CW_;

    const int tid  = threadIdx.x;
    const int wid  = tid >> 5;        // 16 warps; warp wid owns window slot wid
    const int lane = tid & 31;

    const int dh  = wid >> 2;
    const int dw  = wid & 3;
    const int row = (Hc * KER_ + dh) * OW_ + (Wc * KER_ + dw);

    const float4* r4 = reinterpret_cast<const float4*>(
        orig + ((size_t)b * (OH_ * OW_) + row) * D_);
    const float4* c4 = reinterpret_cast<const float4*>(
        comp + (size_t)blk * D_);

    // Each warp redundantly accumulates ||c||^2 alongside its dot product:
    // no SMEM staging of c, no block-wide barrier before the streaming loads.
    // The 16 warps read identical c addresses -> L1 pending-hit merge; DRAM
    // traffic is unchanged and all loads issue immediately at CTA start.
    float dot = 0.f, rr = 0.f, cc = 0.f;
    #pragma unroll
    for (int i = 0; i < 8; i++) {
        float4 r = r4[lane + i * 32];
        float4 c = c4[lane + i * 32];
        dot += r.x * c.x + r.y * c.y + r.z * c.z + r.w * c.w;
        rr  += r.x * r.x + r.y * r.y + r.z * r.z + r.w * r.w;
        cc  += c.x * c.x + c.y * c.y + c.z * c.z + c.w * c.w;
    }
    #pragma unroll
    for (int o = 16; o > 0; o >>= 1) {
        dot += __shfl_xor_sync(0xffffffffu, dot, o);
        rr  += __shfl_xor_sync(0xffffffffu, rr,  o);
        cc  += __shfl_xor_sync(0xffffffffu, cc,  o);
    }
    if (lane == 0) {
        s_sims[wid] = dot / (fmaxf(sqrtf(cc), EPS_) * fmaxf(sqrtf(rr), EPS_));
    }
    __syncthreads();

    // --- block sum -> global atomic; last finished block writes the loss ---
    if (tid == 0) {
        float s = 0.f;
        #pragma unroll
        for (int i = 0; i < 16; i++) s += s_sims[i];
        atomicAdd(&g_accum, s);
        __threadfence();
        unsigned prev = atomicAdd(&g_count, 1u);
        if (prev == (unsigned)(NB_ - 1)) {
            // All adds are visible (fence before each counter bump).
            float tot = g_accum;
            out[0] = 1.0f - tot / (float)(NB_ * WIN_);
            // Reset for the next graph replay.
            g_accum = 0.0f;
            __threadfence();
            g_count = 0u;
        }
    }
}

extern "C" void kernel_launch(void* const* d_in, const int* in_sizes, int n_in,
                              void* d_out, int out_size) {
    const float* comp = (const float*)d_in[0];
    const float* orig = (const float*)d_in[1];
    rf_sim_kernel<<<NB_, 512>>>(comp, orig, (float*)d_out);
}